// round 5
// baseline (speedup 1.0000x reference)
#include <cuda_runtime.h>
#include <cuda_bf16.h>

// DWT_1D haar: lfc[k] = l0*x[2k] + l1*x[2k+1]; hfc[k] = h0*x[2k] + h1*x[2k+1]
// Coefficients read from matrix_low[0..1] / matrix_high[0..1].
// Pure streaming: 64 MiB read + 64 MiB write.
// This version front-batches 8 LDG.128 per thread (MLP_p1=8) before any
// dependent math, to keep the L1tex wavefront queue full.

__global__ void __launch_bounds__(256) dwt1d_haar_kernel(
    const float4* __restrict__ x4,
    const float* __restrict__ ml,
    const float* __restrict__ mh,
    float4* __restrict__ out_low,
    float4* __restrict__ out_high,
    int total_out4)                    // float4 outputs per side (2M)
{
    const int nthreads = gridDim.x * blockDim.x;   // total_out4 / 4
    const int tid = blockIdx.x * blockDim.x + threadIdx.x;

    const float l0 = ml[0], l1 = ml[1];
    const float h0 = mh[0], h1 = mh[1];

    // 4 output-float4 slots per side, strided by nthreads (coalesced).
    int i0 = tid;
    int i1 = tid + nthreads;
    int i2 = tid + 2 * nthreads;
    int i3 = tid + 3 * nthreads;

    // Front-batch all 8 global loads (independent -> 8 outstanding LDG.128).
    float4 a0 = __ldcs(&x4[2 * i0]);
    float4 a1 = __ldcs(&x4[2 * i0 + 1]);
    float4 b0 = __ldcs(&x4[2 * i1]);
    float4 b1 = __ldcs(&x4[2 * i1 + 1]);
    float4 c0 = __ldcs(&x4[2 * i2]);
    float4 c1 = __ldcs(&x4[2 * i2 + 1]);
    float4 d0 = __ldcs(&x4[2 * i3]);
    float4 d1 = __ldcs(&x4[2 * i3 + 1]);

    float4 lo, hi;

    lo.x = l0 * a0.x + l1 * a0.y;  hi.x = h0 * a0.x + h1 * a0.y;
    lo.y = l0 * a0.z + l1 * a0.w;  hi.y = h0 * a0.z + h1 * a0.w;
    lo.z = l0 * a1.x + l1 * a1.y;  hi.z = h0 * a1.x + h1 * a1.y;
    lo.w = l0 * a1.z + l1 * a1.w;  hi.w = h0 * a1.z + h1 * a1.w;
    __stcs(&out_low[i0],  lo);
    __stcs(&out_high[i0], hi);

    lo.x = l0 * b0.x + l1 * b0.y;  hi.x = h0 * b0.x + h1 * b0.y;
    lo.y = l0 * b0.z + l1 * b0.w;  hi.y = h0 * b0.z + h1 * b0.w;
    lo.z = l0 * b1.x + l1 * b1.y;  hi.z = h0 * b1.x + h1 * b1.y;
    lo.w = l0 * b1.z + l1 * b1.w;  hi.w = h0 * b1.z + h1 * b1.w;
    __stcs(&out_low[i1],  lo);
    __stcs(&out_high[i1], hi);

    lo.x = l0 * c0.x + l1 * c0.y;  hi.x = h0 * c0.x + h1 * c0.y;
    lo.y = l0 * c0.z + l1 * c0.w;  hi.y = h0 * c0.z + h1 * c0.w;
    lo.z = l0 * c1.x + l1 * c1.y;  hi.z = h0 * c1.x + h1 * c1.y;
    lo.w = l0 * c1.z + l1 * c1.w;  hi.w = h0 * c1.z + h1 * c1.w;
    __stcs(&out_low[i2],  lo);
    __stcs(&out_high[i2], hi);

    lo.x = l0 * d0.x + l1 * d0.y;  hi.x = h0 * d0.x + h1 * d0.y;
    lo.y = l0 * d0.z + l1 * d0.w;  hi.y = h0 * d0.z + h1 * d0.w;
    lo.z = l0 * d1.x + l1 * d1.y;  hi.z = h0 * d1.x + h1 * d1.y;
    lo.w = l0 * d1.z + l1 * d1.w;  hi.w = h0 * d1.z + h1 * d1.w;
    __stcs(&out_low[i3],  lo);
    __stcs(&out_high[i3], hi);
}

extern "C" void kernel_launch(void* const* d_in, const int* in_sizes, int n_in,
                              void* d_out, int out_size) {
    const float* x  = (const float*)d_in[0];   // [32,64,8192] f32
    const float* ml = (const float*)d_in[1];   // [4096,8192] f32
    const float* mh = (const float*)d_in[2];   // [4096,8192] f32
    float* out = (float*)d_out;                // [lfc | hfc]

    const int half = out_size / 2;             // 8388608 lfc elements
    const int total_out4 = half / 4;           // 2097152 float4 per side
    (void)n_in; (void)in_sizes;

    const int threads = 256;
    const int nthreads = total_out4 / 4;       // 524288 (exact divide)
    const int blocks = nthreads / threads;     // 2048

    dwt1d_haar_kernel<<<blocks, threads>>>(
        (const float4*)x, ml, mh,
        (float4*)out, (float4*)(out + half),
        total_out4);
}

// round 6
// speedup vs baseline: 1.0833x; 1.0833x over previous
#include <cuda_runtime.h>
#include <cuda_bf16.h>
#include <cstdint>

// DWT_1D haar: lfc[k] = l0*x[2k] + l1*x[2k+1]; hfc[k] = h0*x[2k] + h1*x[2k+1]
// (coefficients read from matrix_low[0..1] / matrix_high[0..1]).
// Pure streaming problem (64 MiB in, 64 MiB out). LDG versions plateau at
// ~18.3us kernel (issue 13%, all stall_long_scoreboard). This version uses an
// async bulk-copy (TMA/UBLKCP) double-buffered pipeline: loads are fully
// async into smem with mbarrier completion, compute reads smem, stores go out
// via streaming STG.128 (fire-and-forget). Load latency leaves the critical
// path entirely.

#define CHUNK_F4   1024                 // float4 per chunk = 16 KiB
#define CHUNK_BYTES 16384
#define OUT_F4     512                  // float4 outputs per side per chunk
#define NTHREADS   256

__device__ __forceinline__ uint32_t smem_u32(const void* p) {
    uint32_t a;
    asm("{ .reg .u64 t; cvta.to.shared.u64 t, %1; cvt.u32.u64 %0, t; }"
        : "=r"(a) : "l"(p));
    return a;
}

__device__ __forceinline__ void mbar_init(uint32_t mbar, uint32_t count) {
    asm volatile("mbarrier.init.shared.b64 [%0], %1;" :: "r"(mbar), "r"(count) : "memory");
}

__device__ __forceinline__ void mbar_expect_tx(uint32_t mbar, uint32_t bytes) {
    asm volatile("mbarrier.arrive.expect_tx.shared.b64 _, [%0], %1;"
                 :: "r"(mbar), "r"(bytes) : "memory");
}

__device__ __forceinline__ void mbar_wait(uint32_t mbar, uint32_t parity) {
    asm volatile(
        "{\n\t"
        ".reg .pred P;\n\t"
        "WAIT_%=:\n\t"
        "mbarrier.try_wait.parity.acquire.cta.shared::cta.b64 P, [%0], %1, 0x989680;\n\t"
        "@P bra.uni DONE_%=;\n\t"
        "bra.uni WAIT_%=;\n\t"
        "DONE_%=:\n\t"
        "}"
        :: "r"(mbar), "r"(parity) : "memory");
}

__device__ __forceinline__ void bulk_ld(uint32_t dst_smem, const void* src_gmem,
                                        uint32_t bytes, uint32_t mbar) {
    asm volatile(
        "cp.async.bulk.shared::cta.global.mbarrier::complete_tx::bytes [%0], [%1], %2, [%3];"
        :: "r"(dst_smem), "l"(src_gmem), "r"(bytes), "r"(mbar) : "memory");
}

__global__ void __launch_bounds__(NTHREADS) dwt1d_haar_tma_kernel(
    const float4* __restrict__ x4,
    const float* __restrict__ ml,
    const float* __restrict__ mh,
    float4* __restrict__ out_low,
    float4* __restrict__ out_high,
    int nchunks)
{
    __shared__ __align__(16) float4 buf[2][CHUNK_F4];          // 2 x 16 KiB
    __shared__ __align__(8) unsigned long long mbar_store[2];

    const int tid = threadIdx.x;
    const uint32_t mb0 = smem_u32(&mbar_store[0]);
    const uint32_t mb1 = smem_u32(&mbar_store[1]);
    const uint32_t bufa0 = smem_u32(&buf[0][0]);
    const uint32_t bufa1 = smem_u32(&buf[1][0]);

    if (tid == 0) {
        mbar_init(mb0, 1);
        mbar_init(mb1, 1);
    }
    __syncthreads();

    const float l0 = ml[0], l1 = ml[1];
    const float h0 = mh[0], h1 = mh[1];

    // Prologue: issue loads for my first two chunks.
    if (tid == 0) {
        int c0 = blockIdx.x;
        if (c0 < nchunks) {
            mbar_expect_tx(mb0, CHUNK_BYTES);
            bulk_ld(bufa0, x4 + (size_t)c0 * CHUNK_F4, CHUNK_BYTES, mb0);
        }
        int c1 = blockIdx.x + gridDim.x;
        if (c1 < nchunks) {
            mbar_expect_tx(mb1, CHUNK_BYTES);
            bulk_ld(bufa1, x4 + (size_t)c1 * CHUNK_F4, CHUNK_BYTES, mb1);
        }
    }

    for (int k = 0;; ++k) {
        int c = blockIdx.x + k * gridDim.x;
        if (c >= nchunks) break;

        const int stage = k & 1;
        const uint32_t parity = (k >> 1) & 1;
        mbar_wait(stage ? mb1 : mb0, parity);

        // Compute: thread handles output float4 slots j = tid, tid+256 of this
        // chunk. Input float4s 2j, 2j+1 hold 8 consecutive floats.
        const int base = c * OUT_F4;
        const float4* __restrict__ s = buf[stage];

        float4 a0 = s[2 * tid];
        float4 a1 = s[2 * tid + 1];
        float4 b0 = s[2 * (tid + NTHREADS)];
        float4 b1 = s[2 * (tid + NTHREADS) + 1];

        float4 lo, hi;
        lo.x = l0 * a0.x + l1 * a0.y;  hi.x = h0 * a0.x + h1 * a0.y;
        lo.y = l0 * a0.z + l1 * a0.w;  hi.y = h0 * a0.z + h1 * a0.w;
        lo.z = l0 * a1.x + l1 * a1.y;  hi.z = h0 * a1.x + h1 * a1.y;
        lo.w = l0 * a1.z + l1 * a1.w;  hi.w = h0 * a1.z + h1 * a1.w;
        __stcs(&out_low[base + tid], lo);
        __stcs(&out_high[base + tid], hi);

        lo.x = l0 * b0.x + l1 * b0.y;  hi.x = h0 * b0.x + h1 * b0.y;
        lo.y = l0 * b0.z + l1 * b0.w;  hi.y = h0 * b0.z + h1 * b0.w;
        lo.z = l0 * b1.x + l1 * b1.y;  hi.z = h0 * b1.x + h1 * b1.y;
        lo.w = l0 * b1.z + l1 * b1.w;  hi.w = h0 * b1.z + h1 * b1.w;
        __stcs(&out_low[base + tid + NTHREADS], lo);
        __stcs(&out_high[base + tid + NTHREADS], hi);

        __syncthreads();  // everyone done reading buf[stage]

        // Refill this stage with chunk k+2.
        if (tid == 0) {
            int cn = blockIdx.x + (k + 2) * gridDim.x;
            if (cn < nchunks) {
                uint32_t mb = stage ? mb1 : mb0;
                mbar_expect_tx(mb, CHUNK_BYTES);
                bulk_ld(stage ? bufa1 : bufa0,
                        x4 + (size_t)cn * CHUNK_F4, CHUNK_BYTES, mb);
            }
        }
    }
}

extern "C" void kernel_launch(void* const* d_in, const int* in_sizes, int n_in,
                              void* d_out, int out_size) {
    const float* x  = (const float*)d_in[0];   // [32,64,8192] f32
    const float* ml = (const float*)d_in[1];   // [4096,8192] f32
    const float* mh = (const float*)d_in[2];   // [4096,8192] f32
    float* out = (float*)d_out;                // [lfc | hfc]

    const int in_elems = in_sizes[0];          // 16777216
    const int half = out_size / 2;             // 8388608 lfc elements
    const int nchunks = in_elems / (CHUNK_F4 * 4);   // 4096
    (void)n_in;

    const int grid = 1024;                     // 4 chunks per CTA exactly

    dwt1d_haar_tma_kernel<<<grid, NTHREADS>>>(
        (const float4*)x, ml, mh,
        (float4*)out, (float4*)(out + half),
        nchunks);
}